// round 2
// baseline (speedup 1.0000x reference)
#include <cuda_runtime.h>
#include <math.h>

// Problem dims (fixed by the reference)
#define B_DIM 4
#define T_DIM 2048
#define C_DIM 1024
#define H_DIM 16
#define D_DIM 64
#define M_ROWS (B_DIM * T_DIM)   // 8192
#define ATTN_SCALE 0.125f        // 1/sqrt(64)

// ---------------------------------------------------------------------------
// Scratch (no allocations allowed -> device globals)
// ---------------------------------------------------------------------------
__device__ float g_q[M_ROWS * C_DIM];
__device__ float g_k[M_ROWS * C_DIM];
__device__ float g_v[M_ROWS * C_DIM];
__device__ float g_att[M_ROWS * C_DIM];

// ---------------------------------------------------------------------------
// GEMM: C[m][n] = sum_k A[m][k] * W[n][k] + bias[n]
// A: [8192,1024] row-major, W: [1024,1024] row-major (torch Linear weight)
// Tile 128x128, BK=16, 256 threads, 8x8 micro-tile (split 4+4 for coalesced
// float4 epilogue), smem padded to stride 17 for conflict-free fragment reads.
// ---------------------------------------------------------------------------
__device__ __forceinline__ void gemm_body(
    const float* __restrict__ A, const float* __restrict__ W,
    const float* __restrict__ bias, float* __restrict__ Cout)
{
    const int K = C_DIM;
    const int N = C_DIM;
    __shared__ float As[128][17];
    __shared__ float Ws[128][17];

    const int tid = threadIdx.x;
    const int tx = tid & 15;
    const int ty = tid >> 4;
    const int m0 = blockIdx.y * 128;
    const int n0 = blockIdx.x * 128;

    float acc[8][8];
#pragma unroll
    for (int i = 0; i < 8; i++)
#pragma unroll
        for (int j = 0; j < 8; j++) acc[i][j] = 0.f;

    for (int k0 = 0; k0 < K; k0 += 16) {
#pragma unroll
        for (int l = 0; l < 2; l++) {
            const int f = tid + 256 * l;         // 0..511
            const int row = f >> 2;              // 0..127
            const int kq = (f & 3) << 2;         // 0,4,8,12
            const float4 va = *(const float4*)(A + (size_t)(m0 + row) * K + k0 + kq);
            As[row][kq + 0] = va.x; As[row][kq + 1] = va.y;
            As[row][kq + 2] = va.z; As[row][kq + 3] = va.w;
            const float4 vw = *(const float4*)(W + (size_t)(n0 + row) * K + k0 + kq);
            Ws[row][kq + 0] = vw.x; Ws[row][kq + 1] = vw.y;
            Ws[row][kq + 2] = vw.z; Ws[row][kq + 3] = vw.w;
        }
        __syncthreads();

#pragma unroll
        for (int k = 0; k < 16; k++) {
            float a[8], bfrag[8];
#pragma unroll
            for (int i = 0; i < 4; i++) {
                a[i]     = As[ty * 4 + i][k];
                a[4 + i] = As[64 + ty * 4 + i][k];
                bfrag[i]     = Ws[tx * 4 + i][k];
                bfrag[4 + i] = Ws[64 + tx * 4 + i][k];
            }
#pragma unroll
            for (int i = 0; i < 8; i++)
#pragma unroll
                for (int j = 0; j < 8; j++)
                    acc[i][j] = fmaf(a[i], bfrag[j], acc[i][j]);
        }
        __syncthreads();
    }

#pragma unroll
    for (int i = 0; i < 8; i++) {
        const int row = m0 + ((i < 4) ? (ty * 4 + i) : (64 + ty * 4 + (i - 4)));
#pragma unroll
        for (int jg = 0; jg < 2; jg++) {
            const int col = n0 + jg * 64 + tx * 4;
            const float4 bb = *(const float4*)(bias + col);
            float4 o;
            o.x = acc[i][jg * 4 + 0] + bb.x;
            o.y = acc[i][jg * 4 + 1] + bb.y;
            o.z = acc[i][jg * 4 + 2] + bb.z;
            o.w = acc[i][jg * 4 + 3] + bb.w;
            *(float4*)(Cout + (size_t)row * N + col) = o;
        }
    }
}

__global__ __launch_bounds__(256) void gemm_qkv_kernel(
    const float* __restrict__ q_in, const float* __restrict__ k_in,
    const float* __restrict__ v_in,
    const float* __restrict__ Wq, const float* __restrict__ Wk,
    const float* __restrict__ Wv,
    const float* __restrict__ bq, const float* __restrict__ bk,
    const float* __restrict__ bv)
{
    const float* A; const float* W; const float* bias; float* Cp;
    if (blockIdx.z == 0)      { A = q_in; W = Wq; bias = bq; Cp = g_q; }
    else if (blockIdx.z == 1) { A = k_in; W = Wk; bias = bk; Cp = g_k; }
    else                      { A = v_in; W = Wv; bias = bv; Cp = g_v; }
    gemm_body(A, W, bias, Cp);
}

__global__ __launch_bounds__(256) void gemm_out_kernel(
    const float* __restrict__ Wo, const float* __restrict__ bo,
    float* __restrict__ out)
{
    gemm_body(g_att, Wo, bo, out);
}

// ---------------------------------------------------------------------------
// Flash attention, fp32. One block = (b, h, 128 q-rows). 256 threads.
// K-tiles of 64. Online softmax. Smem: Qs[128][65], Ks[64][65], Vs[64][64],
// Ss[128][65] -> 99584 B dynamic, 2 CTAs/SM.
// Thread roles:
//   S-GEMM stage : 16x16 grid, 8x4 micro-tile (rows split 4+4)
//   softmax/PV   : thread t -> q-row r = t>>1, half = t&1 (32 cols / 32 dims)
// ---------------------------------------------------------------------------
#define ATT_SMEM_FLOATS (128 * 65 + 64 * 65 + 64 * 64 + 128 * 65)

__global__ __launch_bounds__(256, 2) void attn_kernel(
    const float* __restrict__ Qg, const float* __restrict__ Kg,
    const float* __restrict__ Vg, float* __restrict__ Og)
{
    extern __shared__ float sm[];
    float* Qs = sm;                    // [128][65]
    float* Ks = Qs + 128 * 65;         // [64][65]
    float* Vs = Ks + 64 * 65;          // [64][64]
    float* Ss = Vs + 64 * 64;          // [128][65]

    const int tid = threadIdx.x;
    const int tx = tid & 15;
    const int ty = tid >> 4;
    const int tq0 = blockIdx.x * 128;
    const int h = blockIdx.y;
    const int b = blockIdx.z;

    const size_t baseQ  = ((size_t)b * T_DIM + tq0) * C_DIM + h * D_DIM;
    const size_t baseKV = ((size_t)b * T_DIM) * C_DIM + h * D_DIM;

    // Load Q tile (scaled): 128 rows x 64 floats = 2048 float4
#pragma unroll
    for (int l = 0; l < 8; l++) {
        const int f = tid + 256 * l;
        const int row = f >> 4;
        const int dq = (f & 15) << 2;
        const float4 v = *(const float4*)(Qg + baseQ + (size_t)row * C_DIM + dq);
        float* qp = Qs + row * 65 + dq;
        qp[0] = v.x * ATTN_SCALE; qp[1] = v.y * ATTN_SCALE;
        qp[2] = v.z * ATTN_SCALE; qp[3] = v.w * ATTN_SCALE;
    }

    const int r = tid >> 1;
    const int half = tid & 1;
    const int d0 = half * 32;   // owned output dims
    const int c0 = half * 32;   // owned score cols

    float mi = -INFINITY;
    float li = 0.f;
    float acc[32];
#pragma unroll
    for (int i = 0; i < 32; i++) acc[i] = 0.f;

    for (int kt = 0; kt < T_DIM / 64; kt++) {
        __syncthreads();
        // Load K,V tile: 64x64 each
#pragma unroll
        for (int l = 0; l < 4; l++) {
            const int f = tid + 256 * l;
            const int row = f >> 4;
            const int dq = (f & 15) << 2;
            const size_t g = baseKV + (size_t)(kt * 64 + row) * C_DIM + dq;
            const float4 kv = *(const float4*)(Kg + g);
            float* kp = Ks + row * 65 + dq;
            kp[0] = kv.x; kp[1] = kv.y; kp[2] = kv.z; kp[3] = kv.w;
            const float4 vv = *(const float4*)(Vg + g);
            *(float4*)(Vs + row * 64 + dq) = vv;
        }
        __syncthreads();

        // S = (scaled Q) . K^T : 128x64
        float s[8][4];
#pragma unroll
        for (int i = 0; i < 8; i++)
#pragma unroll
            for (int j = 0; j < 4; j++) s[i][j] = 0.f;

#pragma unroll 8
        for (int d = 0; d < 64; d++) {
            float a[8], bb[4];
#pragma unroll
            for (int i = 0; i < 4; i++) {
                a[i]     = Qs[(ty * 4 + i) * 65 + d];
                a[4 + i] = Qs[(64 + ty * 4 + i) * 65 + d];
                bb[i]    = Ks[(tx * 4 + i) * 65 + d];
            }
#pragma unroll
            for (int i = 0; i < 8; i++)
#pragma unroll
                for (int j = 0; j < 4; j++)
                    s[i][j] = fmaf(a[i], bb[j], s[i][j]);
        }
#pragma unroll
        for (int i = 0; i < 8; i++) {
            const int row = (i < 4) ? (ty * 4 + i) : (64 + ty * 4 + (i - 4));
#pragma unroll
            for (int j = 0; j < 4; j++)
                Ss[row * 65 + tx * 4 + j] = s[i][j];
        }
        __syncthreads();

        // Online softmax: thread (r, half) owns cols [c0, c0+32)
        float tmax = -INFINITY;
#pragma unroll
        for (int c = 0; c < 32; c++)
            tmax = fmaxf(tmax, Ss[r * 65 + c0 + c]);
        tmax = fmaxf(tmax, __shfl_xor_sync(0xffffffffu, tmax, 1));
        const float mnew = fmaxf(mi, tmax);
        const float corr = __expf(mi - mnew);
        li *= corr;
#pragma unroll
        for (int i = 0; i < 32; i++) acc[i] *= corr;
        float rsum = 0.f;
#pragma unroll
        for (int c = 0; c < 32; c++) {
            const float p = __expf(Ss[r * 65 + c0 + c] - mnew);
            Ss[r * 65 + c0 + c] = p;
            rsum += p;
        }
        rsum += __shfl_xor_sync(0xffffffffu, rsum, 1);
        li += rsum;
        mi = mnew;
        __syncwarp();   // partner (lane^1) wrote other half of the row

        // acc += P . V  (thread owns dims [d0, d0+32) of row r)
#pragma unroll 4
        for (int j = 0; j < 64; j++) {
            const float p = Ss[r * 65 + j];
            const float4* vp = (const float4*)(Vs + j * 64 + d0);
#pragma unroll
            for (int q4 = 0; q4 < 8; q4++) {
                const float4 vv = vp[q4];
                acc[q4 * 4 + 0] = fmaf(p, vv.x, acc[q4 * 4 + 0]);
                acc[q4 * 4 + 1] = fmaf(p, vv.y, acc[q4 * 4 + 1]);
                acc[q4 * 4 + 2] = fmaf(p, vv.z, acc[q4 * 4 + 2]);
                acc[q4 * 4 + 3] = fmaf(p, vv.w, acc[q4 * 4 + 3]);
            }
        }
    }

    const float inv = 1.f / li;
    const size_t ob = baseQ + (size_t)r * C_DIM + d0;
#pragma unroll
    for (int q4 = 0; q4 < 8; q4++) {
        float4 o;
        o.x = acc[q4 * 4 + 0] * inv;
        o.y = acc[q4 * 4 + 1] * inv;
        o.z = acc[q4 * 4 + 2] * inv;
        o.w = acc[q4 * 4 + 3] * inv;
        *(float4*)(Og + ob + q4 * 4) = o;
    }
}

// ---------------------------------------------------------------------------
// Launch
// ---------------------------------------------------------------------------
extern "C" void kernel_launch(void* const* d_in, const int* in_sizes, int n_in,
                              void* d_out, int out_size)
{
    (void)in_sizes; (void)n_in; (void)out_size;
    const float* query = (const float*)d_in[0];
    const float* key_i = (const float*)d_in[1];
    const float* value = (const float*)d_in[2];
    const float* Wq = (const float*)d_in[3];
    const float* bq = (const float*)d_in[4];
    const float* Wk = (const float*)d_in[5];
    const float* bk = (const float*)d_in[6];
    const float* Wv = (const float*)d_in[7];
    const float* bv = (const float*)d_in[8];
    const float* Wo = (const float*)d_in[9];
    const float* bo = (const float*)d_in[10];
    float* out = (float*)d_out;

    float *gq, *gk, *gv, *gatt;
    cudaGetSymbolAddress((void**)&gq, g_q);
    cudaGetSymbolAddress((void**)&gk, g_k);
    cudaGetSymbolAddress((void**)&gv, g_v);
    cudaGetSymbolAddress((void**)&gatt, g_att);

    const int attn_smem = ATT_SMEM_FLOATS * (int)sizeof(float);  // 99584 B
    cudaFuncSetAttribute(attn_kernel,
                         cudaFuncAttributeMaxDynamicSharedMemorySize, attn_smem);

    // 1) QKV projections: grid.z picks q/k/v
    dim3 gqkv(C_DIM / 128, M_ROWS / 128, 3);
    gemm_qkv_kernel<<<gqkv, 256>>>(query, key_i, value, Wq, Wk, Wv, bq, bk, bv);

    // 2) attention per (b, h, 128 q-rows)
    dim3 gatt_grid(T_DIM / 128, H_DIM, B_DIM);
    attn_kernel<<<gatt_grid, 256, attn_smem>>>(gq, gk, gv, gatt);

    // 3) output projection
    dim3 gout(C_DIM / 128, M_ROWS / 128);
    gemm_out_kernel<<<gout, 256>>>(Wo, bo, out);
}

// round 3
// speedup vs baseline: 4.3084x; 4.3084x over previous
#include <cuda_runtime.h>
#include <math.h>

#define B_DIM 4
#define T_DIM 2048
#define C_DIM 1024
#define H_DIM 16
#define D_DIM 64
#define M_ROWS (B_DIM * T_DIM)   // 8192
#define ATTN_SCALE 0.125f

// ---------------------------------------------------------------------------
// Scratch
// ---------------------------------------------------------------------------
__device__ float g_q[M_ROWS * C_DIM];
__device__ float g_k[M_ROWS * C_DIM];
__device__ float g_v[M_ROWS * C_DIM];
__device__ float g_att[M_ROWS * C_DIM];

// ---------------------------------------------------------------------------
// tf32 helpers
// ---------------------------------------------------------------------------
__device__ __forceinline__ unsigned f2tf32(float f) {
    unsigned u;
    asm("cvt.rna.tf32.f32 %0, %1;" : "=r"(u) : "f"(f));
    return u;
}

// D += A(16x8,row) * B(8x8,col)  tf32 -> f32
__device__ __forceinline__ void mma_tf32(float* c, const unsigned* a, const unsigned* b) {
    asm volatile(
        "mma.sync.aligned.m16n8k8.row.col.f32.tf32.tf32.f32 "
        "{%0,%1,%2,%3}, {%4,%5,%6,%7}, {%8,%9}, {%0,%1,%2,%3};"
        : "+f"(c[0]), "+f"(c[1]), "+f"(c[2]), "+f"(c[3])
        : "r"(a[0]), "r"(a[1]), "r"(a[2]), "r"(a[3]), "r"(b[0]), "r"(b[1]));
}

// ---------------------------------------------------------------------------
// GEMM: C[m][n] = sum_k A[m][k] * W[n][k] + bias[n]   (tf32 tensor-core)
// CTA tile 128x128, BK=16, 8 warps (2x4), warp tile 64x32.
// Smem stride 20 -> conflict-free 8-row x 4-col fragment loads.
// ---------------------------------------------------------------------------
__device__ __forceinline__ void gemm_body_tc(
    const float* __restrict__ A, const float* __restrict__ W,
    const float* __restrict__ bias, float* __restrict__ Cout)
{
    const int K = C_DIM;
    const int N = C_DIM;
    __shared__ unsigned As[128][20];
    __shared__ unsigned Ws[128][20];

    const int tid  = threadIdx.x;
    const int lane = tid & 31;
    const int w    = tid >> 5;
    const int g    = lane >> 2;   // 0..7
    const int t    = lane & 3;    // 0..3
    const int wm   = (w >> 2) * 64;
    const int wn   = (w & 3) * 32;
    const int m0   = blockIdx.y * 128;
    const int n0   = blockIdx.x * 128;

    float acc[4][4][4];
#pragma unroll
    for (int mt = 0; mt < 4; mt++)
#pragma unroll
        for (int nt = 0; nt < 4; nt++)
#pragma unroll
            for (int j = 0; j < 4; j++) acc[mt][nt][j] = 0.f;

    for (int k0 = 0; k0 < K; k0 += 16) {
#pragma unroll
        for (int l = 0; l < 2; l++) {
            const int f = tid + 256 * l;
            const int row = f >> 2;
            const int kq = (f & 3) << 2;
            const float4 va = *(const float4*)(A + (size_t)(m0 + row) * K + k0 + kq);
            As[row][kq + 0] = f2tf32(va.x); As[row][kq + 1] = f2tf32(va.y);
            As[row][kq + 2] = f2tf32(va.z); As[row][kq + 3] = f2tf32(va.w);
            const float4 vw = *(const float4*)(W + (size_t)(n0 + row) * K + k0 + kq);
            Ws[row][kq + 0] = f2tf32(vw.x); Ws[row][kq + 1] = f2tf32(vw.y);
            Ws[row][kq + 2] = f2tf32(vw.z); Ws[row][kq + 3] = f2tf32(vw.w);
        }
        __syncthreads();

#pragma unroll
        for (int kk = 0; kk < 16; kk += 8) {
            unsigned a[4][4], b[4][2];
#pragma unroll
            for (int mt = 0; mt < 4; mt++) {
                const int r = wm + mt * 16 + g;
                a[mt][0] = As[r][kk + t];
                a[mt][1] = As[r + 8][kk + t];
                a[mt][2] = As[r][kk + t + 4];
                a[mt][3] = As[r + 8][kk + t + 4];
            }
#pragma unroll
            for (int nt = 0; nt < 4; nt++) {
                const int n = wn + nt * 8 + g;
                b[nt][0] = Ws[n][kk + t];
                b[nt][1] = Ws[n][kk + t + 4];
            }
#pragma unroll
            for (int mt = 0; mt < 4; mt++)
#pragma unroll
                for (int nt = 0; nt < 4; nt++)
                    mma_tf32(acc[mt][nt], a[mt], b[nt]);
        }
        __syncthreads();
    }

#pragma unroll
    for (int mt = 0; mt < 4; mt++) {
        const int r_lo = m0 + wm + mt * 16 + g;
#pragma unroll
        for (int nt = 0; nt < 4; nt++) {
            const int cc = n0 + wn + nt * 8 + t * 2;
            const float b0 = bias[cc], b1 = bias[cc + 1];
            float2 o;
            o.x = acc[mt][nt][0] + b0; o.y = acc[mt][nt][1] + b1;
            *(float2*)(Cout + (size_t)r_lo * N + cc) = o;
            o.x = acc[mt][nt][2] + b0; o.y = acc[mt][nt][3] + b1;
            *(float2*)(Cout + (size_t)(r_lo + 8) * N + cc) = o;
        }
    }
}

__global__ __launch_bounds__(256) void gemm_qkv_kernel(
    const float* __restrict__ q_in, const float* __restrict__ k_in,
    const float* __restrict__ v_in,
    const float* __restrict__ Wq, const float* __restrict__ Wk,
    const float* __restrict__ Wv,
    const float* __restrict__ bq, const float* __restrict__ bk,
    const float* __restrict__ bv)
{
    const float* A; const float* W; const float* bias; float* Cp;
    if (blockIdx.z == 0)      { A = q_in; W = Wq; bias = bq; Cp = g_q; }
    else if (blockIdx.z == 1) { A = k_in; W = Wk; bias = bk; Cp = g_k; }
    else                      { A = v_in; W = Wv; bias = bv; Cp = g_v; }
    gemm_body_tc(A, W, bias, Cp);
}

__global__ __launch_bounds__(256) void gemm_out_kernel(
    const float* __restrict__ Wo, const float* __restrict__ bo,
    float* __restrict__ out)
{
    gemm_body_tc(g_att, Wo, bo, out);
}

// ---------------------------------------------------------------------------
// FlashAttention-2 style, tf32 tensor cores.
// Block = (b, h, 128 q-rows), 256 threads = 8 warps; warp owns 16 q-rows.
// KV tiles of 64. Softmax entirely in registers (C-fragment row = lane>>2).
// Smem (u32): QP[128][68] (Q tile then reused as P), Ks[64][68], Vs[64][72].
// All fragment-load patterns bank-conflict-free by stride choice.
// ---------------------------------------------------------------------------
#define ATT_SMEM_U32 (128 * 68 + 64 * 68 + 64 * 72)   // 17664 -> 70656 B

__global__ __launch_bounds__(256) void attn_kernel(
    const float* __restrict__ Qg, const float* __restrict__ Kg,
    const float* __restrict__ Vg, float* __restrict__ Og)
{
    extern __shared__ unsigned smu[];
    unsigned* QP = smu;              // [128][68]  Q tile, later P tile
    unsigned* Ks = QP + 128 * 68;    // [64][68]
    unsigned* Vs = Ks + 64 * 68;     // [64][72]

    const int tid  = threadIdx.x;
    const int lane = tid & 31;
    const int w    = tid >> 5;       // 0..7 : rows 16w..16w+15
    const int g    = lane >> 2;
    const int t    = lane & 3;
    const int tq0  = blockIdx.x * 128;
    const int h    = blockIdx.y;
    const int b    = blockIdx.z;

    const size_t baseQ  = ((size_t)b * T_DIM + tq0) * C_DIM + h * D_DIM;
    const size_t baseKV = ((size_t)b * T_DIM) * C_DIM + h * D_DIM;

    // ---- load Q tile (scaled, tf32) into smem ----
#pragma unroll
    for (int l = 0; l < 8; l++) {
        const int f = tid + 256 * l;
        const int row = f >> 4;
        const int dq = (f & 15) << 2;
        const float4 v = *(const float4*)(Qg + baseQ + (size_t)row * C_DIM + dq);
        unsigned* qp = QP + row * 68 + dq;
        qp[0] = f2tf32(v.x * ATTN_SCALE); qp[1] = f2tf32(v.y * ATTN_SCALE);
        qp[2] = f2tf32(v.z * ATTN_SCALE); qp[3] = f2tf32(v.w * ATTN_SCALE);
    }
    __syncthreads();

    // ---- preload Q fragments: 8 k-steps x 4 regs ----
    unsigned qf[8][4];
#pragma unroll
    for (int ks = 0; ks < 8; ks++) {
        const int r = (16 * w + g) * 68;
        qf[ks][0] = QP[r + ks * 8 + t];
        qf[ks][1] = QP[r + 8 * 68 + ks * 8 + t];
        qf[ks][2] = QP[r + ks * 8 + t + 4];
        qf[ks][3] = QP[r + 8 * 68 + ks * 8 + t + 4];
    }

    float mi_lo = -INFINITY, mi_hi = -INFINITY;
    float li_lo = 0.f, li_hi = 0.f;
    float oacc[8][4];
#pragma unroll
    for (int ot = 0; ot < 8; ot++)
#pragma unroll
        for (int j = 0; j < 4; j++) oacc[ot][j] = 0.f;

    for (int kt = 0; kt < T_DIM / 64; kt++) {
        __syncthreads();
        // ---- load K,V tile (tf32) ----
#pragma unroll
        for (int l = 0; l < 4; l++) {
            const int f = tid + 256 * l;
            const int row = f >> 4;
            const int dq = (f & 15) << 2;
            const size_t gidx = baseKV + (size_t)(kt * 64 + row) * C_DIM + dq;
            const float4 kv = *(const float4*)(Kg + gidx);
            unsigned* kp = Ks + row * 68 + dq;
            kp[0] = f2tf32(kv.x); kp[1] = f2tf32(kv.y);
            kp[2] = f2tf32(kv.z); kp[3] = f2tf32(kv.w);
            const float4 vv = *(const float4*)(Vg + gidx);
            unsigned* vp = Vs + row * 72 + dq;
            vp[0] = f2tf32(vv.x); vp[1] = f2tf32(vv.y);
            vp[2] = f2tf32(vv.z); vp[3] = f2tf32(vv.w);
        }
        __syncthreads();

        // ---- S = Qs . K^T : each warp 16x64 ----
        float sacc[8][4];
#pragma unroll
        for (int nt = 0; nt < 8; nt++)
#pragma unroll
            for (int j = 0; j < 4; j++) sacc[nt][j] = 0.f;

#pragma unroll
        for (int ks = 0; ks < 8; ks++) {
            unsigned bf[8][2];
#pragma unroll
            for (int nt = 0; nt < 8; nt++) {
                bf[nt][0] = Ks[(nt * 8 + g) * 68 + ks * 8 + t];
                bf[nt][1] = Ks[(nt * 8 + g) * 68 + ks * 8 + t + 4];
            }
#pragma unroll
            for (int nt = 0; nt < 8; nt++)
                mma_tf32(sacc[nt], qf[ks], bf[nt]);
        }

        // ---- online softmax in registers ----
        float mx_lo = -INFINITY, mx_hi = -INFINITY;
#pragma unroll
        for (int nt = 0; nt < 8; nt++) {
            mx_lo = fmaxf(mx_lo, fmaxf(sacc[nt][0], sacc[nt][1]));
            mx_hi = fmaxf(mx_hi, fmaxf(sacc[nt][2], sacc[nt][3]));
        }
        mx_lo = fmaxf(mx_lo, __shfl_xor_sync(0xffffffffu, mx_lo, 1));
        mx_lo = fmaxf(mx_lo, __shfl_xor_sync(0xffffffffu, mx_lo, 2));
        mx_hi = fmaxf(mx_hi, __shfl_xor_sync(0xffffffffu, mx_hi, 1));
        mx_hi = fmaxf(mx_hi, __shfl_xor_sync(0xffffffffu, mx_hi, 2));

        const float mnew_lo = fmaxf(mi_lo, mx_lo);
        const float mnew_hi = fmaxf(mi_hi, mx_hi);
        const float corr_lo = __expf(mi_lo - mnew_lo);
        const float corr_hi = __expf(mi_hi - mnew_hi);
        mi_lo = mnew_lo; mi_hi = mnew_hi;

        float sum_lo = 0.f, sum_hi = 0.f;
#pragma unroll
        for (int nt = 0; nt < 8; nt++) {
            sacc[nt][0] = __expf(sacc[nt][0] - mi_lo);
            sacc[nt][1] = __expf(sacc[nt][1] - mi_lo);
            sacc[nt][2] = __expf(sacc[nt][2] - mi_hi);
            sacc[nt][3] = __expf(sacc[nt][3] - mi_hi);
            sum_lo += sacc[nt][0] + sacc[nt][1];
            sum_hi += sacc[nt][2] + sacc[nt][3];
        }
        sum_lo += __shfl_xor_sync(0xffffffffu, sum_lo, 1);
        sum_lo += __shfl_xor_sync(0xffffffffu, sum_lo, 2);
        sum_hi += __shfl_xor_sync(0xffffffffu, sum_hi, 1);
        sum_hi += __shfl_xor_sync(0xffffffffu, sum_hi, 2);
        li_lo = li_lo * corr_lo + sum_lo;
        li_hi = li_hi * corr_hi + sum_hi;

#pragma unroll
        for (int ot = 0; ot < 8; ot++) {
            oacc[ot][0] *= corr_lo; oacc[ot][1] *= corr_lo;
            oacc[ot][2] *= corr_hi; oacc[ot][3] *= corr_hi;
        }

        // ---- P -> smem (warp-private rows), then PV mma ----
        {
            const int rbase = (16 * w + g) * 68;
#pragma unroll
            for (int nt = 0; nt < 8; nt++) {
                QP[rbase + nt * 8 + t * 2]           = f2tf32(sacc[nt][0]);
                QP[rbase + nt * 8 + t * 2 + 1]       = f2tf32(sacc[nt][1]);
                QP[rbase + 8 * 68 + nt * 8 + t * 2]     = f2tf32(sacc[nt][2]);
                QP[rbase + 8 * 68 + nt * 8 + t * 2 + 1] = f2tf32(sacc[nt][3]);
            }
        }
        __syncwarp();

#pragma unroll
        for (int ks = 0; ks < 8; ks++) {
            unsigned pa[4];
            const int rbase = (16 * w + g) * 68;
            pa[0] = QP[rbase + ks * 8 + t];
            pa[1] = QP[rbase + 8 * 68 + ks * 8 + t];
            pa[2] = QP[rbase + ks * 8 + t + 4];
            pa[3] = QP[rbase + 8 * 68 + ks * 8 + t + 4];
            unsigned vb[8][2];
#pragma unroll
            for (int ot = 0; ot < 8; ot++) {
                vb[ot][0] = Vs[(ks * 8 + t) * 72 + ot * 8 + g];
                vb[ot][1] = Vs[(ks * 8 + t + 4) * 72 + ot * 8 + g];
            }
#pragma unroll
            for (int ot = 0; ot < 8; ot++)
                mma_tf32(oacc[ot], pa, vb[ot]);
        }
    }

    // ---- epilogue ----
    const float inv_lo = 1.f / li_lo;
    const float inv_hi = 1.f / li_hi;
    const int r_lo = tq0 + 16 * w + g;
    const size_t rowb_lo = ((size_t)b * T_DIM + r_lo) * C_DIM + h * D_DIM;
    const size_t rowb_hi = rowb_lo + (size_t)8 * C_DIM;
#pragma unroll
    for (int ot = 0; ot < 8; ot++) {
        const int cc = ot * 8 + t * 2;
        float2 o;
        o.x = oacc[ot][0] * inv_lo; o.y = oacc[ot][1] * inv_lo;
        *(float2*)(Og + rowb_lo + cc) = o;
        o.x = oacc[ot][2] * inv_hi; o.y = oacc[ot][3] * inv_hi;
        *(float2*)(Og + rowb_hi + cc) = o;
    }
}

// ---------------------------------------------------------------------------
// Launch
// ---------------------------------------------------------------------------
extern "C" void kernel_launch(void* const* d_in, const int* in_sizes, int n_in,
                              void* d_out, int out_size)
{
    (void)in_sizes; (void)n_in; (void)out_size;
    const float* query = (const float*)d_in[0];
    const float* key_i = (const float*)d_in[1];
    const float* value = (const float*)d_in[2];
    const float* Wq = (const float*)d_in[3];
    const float* bq = (const float*)d_in[4];
    const float* Wk = (const float*)d_in[5];
    const float* bk = (const float*)d_in[6];
    const float* Wv = (const float*)d_in[7];
    const float* bv = (const float*)d_in[8];
    const float* Wo = (const float*)d_in[9];
    const float* bo = (const float*)d_in[10];
    float* out = (float*)d_out;

    float *gq, *gk, *gv;
    cudaGetSymbolAddress((void**)&gq, g_q);
    cudaGetSymbolAddress((void**)&gk, g_k);
    cudaGetSymbolAddress((void**)&gv, g_v);
    float* gatt;
    cudaGetSymbolAddress((void**)&gatt, g_att);

    const int attn_smem = ATT_SMEM_U32 * (int)sizeof(unsigned);  // 70656 B
    cudaFuncSetAttribute(attn_kernel,
                         cudaFuncAttributeMaxDynamicSharedMemorySize, attn_smem);

    dim3 gqkv(C_DIM / 128, M_ROWS / 128, 3);
    gemm_qkv_kernel<<<gqkv, 256>>>(query, key_i, value, Wq, Wk, Wv, bq, bk, bv);

    dim3 gatt_grid(T_DIM / 128, H_DIM, B_DIM);
    attn_kernel<<<gatt_grid, 256, attn_smem>>>(gq, gk, gv, gatt);

    dim3 gout(C_DIM / 128, M_ROWS / 128);
    gemm_out_kernel<<<gout, 256>>>(Wo, bo, out);
}

// round 4
// speedup vs baseline: 4.5103x; 1.0469x over previous
#include <cuda_runtime.h>
#include <math.h>

#define B_DIM 4
#define T_DIM 2048
#define C_DIM 1024
#define H_DIM 16
#define D_DIM 64
#define M_ROWS (B_DIM * T_DIM)   // 8192
#define ATTN_SCALE 0.125f

// ---------------------------------------------------------------------------
// Scratch
// ---------------------------------------------------------------------------
__device__ float g_q[M_ROWS * C_DIM];
__device__ float g_k[M_ROWS * C_DIM];
__device__ float g_v[M_ROWS * C_DIM];
__device__ float g_att[M_ROWS * C_DIM];

// ---------------------------------------------------------------------------
// tf32 helpers
// ---------------------------------------------------------------------------
__device__ __forceinline__ unsigned f2tf32(float f) {
    unsigned u;
    asm("cvt.rna.tf32.f32 %0, %1;" : "=r"(u) : "f"(f));
    return u;
}

__device__ __forceinline__ uint4 cvt4(float4 v) {
    uint4 u;
    u.x = f2tf32(v.x); u.y = f2tf32(v.y);
    u.z = f2tf32(v.z); u.w = f2tf32(v.w);
    return u;
}

// D += A(16x8,row) * B(8x8,col)  tf32 -> f32
__device__ __forceinline__ void mma_tf32(float* c, const unsigned* a, const unsigned* b) {
    asm volatile(
        "mma.sync.aligned.m16n8k8.row.col.f32.tf32.tf32.f32 "
        "{%0,%1,%2,%3}, {%4,%5,%6,%7}, {%8,%9}, {%0,%1,%2,%3};"
        : "+f"(c[0]), "+f"(c[1]), "+f"(c[2]), "+f"(c[3])
        : "r"(a[0]), "r"(a[1]), "r"(a[2]), "r"(a[3]), "r"(b[0]), "r"(b[1]));
}

// ---------------------------------------------------------------------------
// GEMM: C[m][n] = sum_k A[m][k] * W[n][k] + bias[n]   (tf32 tensor-core)
// CTA tile 128x128, BK=16, 8 warps (2x4), warp tile 64x32.
// Double-buffered smem (stride 20, STS.128-aligned, conflict-free LDS) with
// register prefetch of the next k-tile.
// ---------------------------------------------------------------------------
__device__ __forceinline__ void gemm_body_tc(
    const float* __restrict__ A, const float* __restrict__ W,
    const float* __restrict__ bias, float* __restrict__ Cout)
{
    const int K = C_DIM;
    const int N = C_DIM;
    __shared__ unsigned As[2][128][20];
    __shared__ unsigned Ws[2][128][20];

    const int tid  = threadIdx.x;
    const int lane = tid & 31;
    const int w    = tid >> 5;
    const int g    = lane >> 2;   // 0..7
    const int t    = lane & 3;    // 0..3
    const int wm   = (w >> 2) * 64;
    const int wn   = (w & 3) * 32;
    const int m0   = blockIdx.y * 128;
    const int n0   = blockIdx.x * 128;

    // per-thread staging coords (2 float4 per operand per tile)
    const int r0 = tid >> 2;                 // rows for l=0 / l=1
    const int r1 = (tid + 256) >> 2;
    const int kq = (tid & 3) << 2;

    const float* Ap0 = A + (size_t)(m0 + r0) * K + kq;
    const float* Ap1 = A + (size_t)(m0 + r1) * K + kq;
    const float* Wp0 = W + (size_t)(n0 + r0) * K + kq;
    const float* Wp1 = W + (size_t)(n0 + r1) * K + kq;

    float acc[4][4][4];
#pragma unroll
    for (int mt = 0; mt < 4; mt++)
#pragma unroll
        for (int nt = 0; nt < 4; nt++)
#pragma unroll
            for (int j = 0; j < 4; j++) acc[mt][nt][j] = 0.f;

    // prologue: tile 0
    {
        float4 pa0 = *(const float4*)(Ap0);
        float4 pa1 = *(const float4*)(Ap1);
        float4 pw0 = *(const float4*)(Wp0);
        float4 pw1 = *(const float4*)(Wp1);
        *(uint4*)&As[0][r0][kq] = cvt4(pa0);
        *(uint4*)&As[0][r1][kq] = cvt4(pa1);
        *(uint4*)&Ws[0][r0][kq] = cvt4(pw0);
        *(uint4*)&Ws[0][r1][kq] = cvt4(pw1);
    }
    __syncthreads();

    const int nIter = K / 16;   // 64
    for (int it = 0; it < nIter; it++) {
        const int cur = it & 1;
        float4 pa0, pa1, pw0, pw1;
        if (it + 1 < nIter) {
            const int ko = (it + 1) * 16;
            pa0 = *(const float4*)(Ap0 + ko);
            pa1 = *(const float4*)(Ap1 + ko);
            pw0 = *(const float4*)(Wp0 + ko);
            pw1 = *(const float4*)(Wp1 + ko);
        }

#pragma unroll
        for (int kk = 0; kk < 16; kk += 8) {
            unsigned a[4][4], b[4][2];
#pragma unroll
            for (int mt = 0; mt < 4; mt++) {
                const int r = wm + mt * 16 + g;
                a[mt][0] = As[cur][r][kk + t];
                a[mt][1] = As[cur][r + 8][kk + t];
                a[mt][2] = As[cur][r][kk + t + 4];
                a[mt][3] = As[cur][r + 8][kk + t + 4];
            }
#pragma unroll
            for (int nt = 0; nt < 4; nt++) {
                const int n = wn + nt * 8 + g;
                b[nt][0] = Ws[cur][n][kk + t];
                b[nt][1] = Ws[cur][n][kk + t + 4];
            }
#pragma unroll
            for (int mt = 0; mt < 4; mt++)
#pragma unroll
                for (int nt = 0; nt < 4; nt++)
                    mma_tf32(acc[mt][nt], a[mt], b[nt]);
        }

        if (it + 1 < nIter) {
            const int nxt = (it + 1) & 1;
            *(uint4*)&As[nxt][r0][kq] = cvt4(pa0);
            *(uint4*)&As[nxt][r1][kq] = cvt4(pa1);
            *(uint4*)&Ws[nxt][r0][kq] = cvt4(pw0);
            *(uint4*)&Ws[nxt][r1][kq] = cvt4(pw1);
            __syncthreads();
        }
    }

#pragma unroll
    for (int mt = 0; mt < 4; mt++) {
        const int r_lo = m0 + wm + mt * 16 + g;
#pragma unroll
        for (int nt = 0; nt < 4; nt++) {
            const int cc = n0 + wn + nt * 8 + t * 2;
            const float b0 = bias[cc], b1 = bias[cc + 1];
            float2 o;
            o.x = acc[mt][nt][0] + b0; o.y = acc[mt][nt][1] + b1;
            *(float2*)(Cout + (size_t)r_lo * N + cc) = o;
            o.x = acc[mt][nt][2] + b0; o.y = acc[mt][nt][3] + b1;
            *(float2*)(Cout + (size_t)(r_lo + 8) * N + cc) = o;
        }
    }
}

__global__ __launch_bounds__(256, 2) void gemm_qkv_kernel(
    const float* __restrict__ q_in, const float* __restrict__ k_in,
    const float* __restrict__ v_in,
    const float* __restrict__ Wq, const float* __restrict__ Wk,
    const float* __restrict__ Wv,
    const float* __restrict__ bq, const float* __restrict__ bk,
    const float* __restrict__ bv)
{
    const float* A; const float* W; const float* bias; float* Cp;
    if (blockIdx.z == 0)      { A = q_in; W = Wq; bias = bq; Cp = g_q; }
    else if (blockIdx.z == 1) { A = k_in; W = Wk; bias = bk; Cp = g_k; }
    else                      { A = v_in; W = Wv; bias = bv; Cp = g_v; }
    gemm_body_tc(A, W, bias, Cp);
}

__global__ __launch_bounds__(256, 2) void gemm_out_kernel(
    const float* __restrict__ Wo, const float* __restrict__ bo,
    float* __restrict__ out)
{
    gemm_body_tc(g_att, Wo, bo, out);
}

// ---------------------------------------------------------------------------
// FlashAttention-2 style, tf32 tensor cores.
// Block = (b, h, 128 q-rows), 256 threads = 8 warps; warp owns 16 q-rows.
// Vectorized staging stores (STS.128), paired P-stores (STS.64).
// ---------------------------------------------------------------------------
#define ATT_SMEM_U32 (128 * 68 + 64 * 68 + 64 * 72)   // 17664 -> 70656 B

__global__ __launch_bounds__(256) void attn_kernel(
    const float* __restrict__ Qg, const float* __restrict__ Kg,
    const float* __restrict__ Vg, float* __restrict__ Og)
{
    extern __shared__ unsigned smu[];
    unsigned* QP = smu;              // [128][68]  Q tile, later P tile
    unsigned* Ks = QP + 128 * 68;    // [64][68]
    unsigned* Vs = Ks + 64 * 68;     // [64][72]

    const int tid  = threadIdx.x;
    const int lane = tid & 31;
    const int w    = tid >> 5;       // 0..7 : rows 16w..16w+15
    const int g    = lane >> 2;
    const int t    = lane & 3;
    const int tq0  = blockIdx.x * 128;
    const int h    = blockIdx.y;
    const int b    = blockIdx.z;

    const size_t baseQ  = ((size_t)b * T_DIM + tq0) * C_DIM + h * D_DIM;
    const size_t baseKV = ((size_t)b * T_DIM) * C_DIM + h * D_DIM;

    // ---- load Q tile (scaled, tf32) into smem: STS.128 ----
#pragma unroll
    for (int l = 0; l < 8; l++) {
        const int f = tid + 256 * l;
        const int row = f >> 4;
        const int dq = (f & 15) << 2;
        float4 v = *(const float4*)(Qg + baseQ + (size_t)row * C_DIM + dq);
        v.x *= ATTN_SCALE; v.y *= ATTN_SCALE; v.z *= ATTN_SCALE; v.w *= ATTN_SCALE;
        *(uint4*)&QP[row * 68 + dq] = cvt4(v);
    }
    __syncthreads();

    // ---- preload Q fragments: 8 k-steps x 4 regs ----
    unsigned qf[8][4];
#pragma unroll
    for (int ks = 0; ks < 8; ks++) {
        const int r = (16 * w + g) * 68;
        qf[ks][0] = QP[r + ks * 8 + t];
        qf[ks][1] = QP[r + 8 * 68 + ks * 8 + t];
        qf[ks][2] = QP[r + ks * 8 + t + 4];
        qf[ks][3] = QP[r + 8 * 68 + ks * 8 + t + 4];
    }

    float mi_lo = -INFINITY, mi_hi = -INFINITY;
    float li_lo = 0.f, li_hi = 0.f;
    float oacc[8][4];
#pragma unroll
    for (int ot = 0; ot < 8; ot++)
#pragma unroll
        for (int j = 0; j < 4; j++) oacc[ot][j] = 0.f;

    for (int kt = 0; kt < T_DIM / 64; kt++) {
        __syncthreads();
        // ---- load K,V tile (tf32), STS.128 ----
#pragma unroll
        for (int l = 0; l < 4; l++) {
            const int f = tid + 256 * l;
            const int row = f >> 4;
            const int dq = (f & 15) << 2;
            const size_t gidx = baseKV + (size_t)(kt * 64 + row) * C_DIM + dq;
            const float4 kv = *(const float4*)(Kg + gidx);
            *(uint4*)&Ks[row * 68 + dq] = cvt4(kv);
            const float4 vv = *(const float4*)(Vg + gidx);
            *(uint4*)&Vs[row * 72 + dq] = cvt4(vv);
        }
        __syncthreads();

        // ---- S = Qs . K^T : each warp 16x64 ----
        float sacc[8][4];
#pragma unroll
        for (int nt = 0; nt < 8; nt++)
#pragma unroll
            for (int j = 0; j < 4; j++) sacc[nt][j] = 0.f;

#pragma unroll
        for (int ks = 0; ks < 8; ks++) {
            unsigned bf[8][2];
#pragma unroll
            for (int nt = 0; nt < 8; nt++) {
                bf[nt][0] = Ks[(nt * 8 + g) * 68 + ks * 8 + t];
                bf[nt][1] = Ks[(nt * 8 + g) * 68 + ks * 8 + t + 4];
            }
#pragma unroll
            for (int nt = 0; nt < 8; nt++)
                mma_tf32(sacc[nt], qf[ks], bf[nt]);
        }

        // ---- online softmax in registers ----
        float mx_lo = -INFINITY, mx_hi = -INFINITY;
#pragma unroll
        for (int nt = 0; nt < 8; nt++) {
            mx_lo = fmaxf(mx_lo, fmaxf(sacc[nt][0], sacc[nt][1]));
            mx_hi = fmaxf(mx_hi, fmaxf(sacc[nt][2], sacc[nt][3]));
        }
        mx_lo = fmaxf(mx_lo, __shfl_xor_sync(0xffffffffu, mx_lo, 1));
        mx_lo = fmaxf(mx_lo, __shfl_xor_sync(0xffffffffu, mx_lo, 2));
        mx_hi = fmaxf(mx_hi, __shfl_xor_sync(0xffffffffu, mx_hi, 1));
        mx_hi = fmaxf(mx_hi, __shfl_xor_sync(0xffffffffu, mx_hi, 2));

        const float mnew_lo = fmaxf(mi_lo, mx_lo);
        const float mnew_hi = fmaxf(mi_hi, mx_hi);
        const float corr_lo = __expf(mi_lo - mnew_lo);
        const float corr_hi = __expf(mi_hi - mnew_hi);
        mi_lo = mnew_lo; mi_hi = mnew_hi;

        float sum_lo = 0.f, sum_hi = 0.f;
#pragma unroll
        for (int nt = 0; nt < 8; nt++) {
            sacc[nt][0] = __expf(sacc[nt][0] - mi_lo);
            sacc[nt][1] = __expf(sacc[nt][1] - mi_lo);
            sacc[nt][2] = __expf(sacc[nt][2] - mi_hi);
            sacc[nt][3] = __expf(sacc[nt][3] - mi_hi);
            sum_lo += sacc[nt][0] + sacc[nt][1];
            sum_hi += sacc[nt][2] + sacc[nt][3];
        }
        sum_lo += __shfl_xor_sync(0xffffffffu, sum_lo, 1);
        sum_lo += __shfl_xor_sync(0xffffffffu, sum_lo, 2);
        sum_hi += __shfl_xor_sync(0xffffffffu, sum_hi, 1);
        sum_hi += __shfl_xor_sync(0xffffffffu, sum_hi, 2);
        li_lo = li_lo * corr_lo + sum_lo;
        li_hi = li_hi * corr_hi + sum_hi;

#pragma unroll
        for (int ot = 0; ot < 8; ot++) {
            oacc[ot][0] *= corr_lo; oacc[ot][1] *= corr_lo;
            oacc[ot][2] *= corr_hi; oacc[ot][3] *= corr_hi;
        }

        // ---- P -> smem (warp-private rows, STS.64 pairs), then PV mma ----
        {
            const int rbase = (16 * w + g) * 68;
#pragma unroll
            for (int nt = 0; nt < 8; nt++) {
                uint2 p0, p1;
                p0.x = f2tf32(sacc[nt][0]); p0.y = f2tf32(sacc[nt][1]);
                p1.x = f2tf32(sacc[nt][2]); p1.y = f2tf32(sacc[nt][3]);
                *(uint2*)&QP[rbase + nt * 8 + t * 2] = p0;
                *(uint2*)&QP[rbase + 8 * 68 + nt * 8 + t * 2] = p1;
            }
        }
        __syncwarp();

#pragma unroll
        for (int ks = 0; ks < 8; ks++) {
            unsigned pa[4];
            const int rbase = (16 * w + g) * 68;
            pa[0] = QP[rbase + ks * 8 + t];
            pa[1] = QP[rbase + 8 * 68 + ks * 8 + t];
            pa[2] = QP[rbase + ks * 8 + t + 4];
            pa[3] = QP[rbase + 8 * 68 + ks * 8 + t + 4];
            unsigned vb[8][2];
#pragma unroll
            for (int ot = 0; ot < 8; ot++) {
                vb[ot][0] = Vs[(ks * 8 + t) * 72 + ot * 8 + g];
                vb[ot][1] = Vs[(ks * 8 + t + 4) * 72 + ot * 8 + g];
            }
#pragma unroll
            for (int ot = 0; ot < 8; ot++)
                mma_tf32(oacc[ot], pa, vb[ot]);
        }
    }

    // ---- epilogue ----
    const float inv_lo = 1.f / li_lo;
    const float inv_hi = 1.f / li_hi;
    const int r_lo = tq0 + 16 * w + g;
    const size_t rowb_lo = ((size_t)b * T_DIM + r_lo) * C_DIM + h * D_DIM;
    const size_t rowb_hi = rowb_lo + (size_t)8 * C_DIM;
#pragma unroll
    for (int ot = 0; ot < 8; ot++) {
        const int cc = ot * 8 + t * 2;
        float2 o;
        o.x = oacc[ot][0] * inv_lo; o.y = oacc[ot][1] * inv_lo;
        *(float2*)(Og + rowb_lo + cc) = o;
        o.x = oacc[ot][2] * inv_hi; o.y = oacc[ot][3] * inv_hi;
        *(float2*)(Og + rowb_hi + cc) = o;
    }
}

// ---------------------------------------------------------------------------
// Launch
// ---------------------------------------------------------------------------
extern "C" void kernel_launch(void* const* d_in, const int* in_sizes, int n_in,
                              void* d_out, int out_size)
{
    (void)in_sizes; (void)n_in; (void)out_size;
    const float* query = (const float*)d_in[0];
    const float* key_i = (const float*)d_in[1];
    const float* value = (const float*)d_in[2];
    const float* Wq = (const float*)d_in[3];
    const float* bq = (const float*)d_in[4];
    const float* Wk = (const float*)d_in[5];
    const float* bk = (const float*)d_in[6];
    const float* Wv = (const float*)d_in[7];
    const float* bv = (const float*)d_in[8];
    const float* Wo = (const float*)d_in[9];
    const float* bo = (const float*)d_in[10];
    float* out = (float*)d_out;

    float *gq, *gk, *gv, *gatt;
    cudaGetSymbolAddress((void**)&gq, g_q);
    cudaGetSymbolAddress((void**)&gk, g_k);
    cudaGetSymbolAddress((void**)&gv, g_v);
    cudaGetSymbolAddress((void**)&gatt, g_att);

    const int attn_smem = ATT_SMEM_U32 * (int)sizeof(unsigned);  // 70656 B
    cudaFuncSetAttribute(attn_kernel,
                         cudaFuncAttributeMaxDynamicSharedMemorySize, attn_smem);

    dim3 gqkv(C_DIM / 128, M_ROWS / 128, 3);
    gemm_qkv_kernel<<<gqkv, 256>>>(query, key_i, value, Wq, Wk, Wv, bq, bk, bv);

    dim3 gatt_grid(T_DIM / 128, H_DIM, B_DIM);
    attn_kernel<<<gatt_grid, 256, attn_smem>>>(gq, gk, gv, gatt);

    dim3 gout(C_DIM / 128, M_ROWS / 128);
    gemm_out_kernel<<<gout, 256>>>(Wo, bo, out);
}